// round 15
// baseline (speedup 1.0000x reference)
#include <cuda_runtime.h>
#include <cuda_fp16.h>
#include <cstdint>

// LSTM cell: single-pass fp16 GEMM (fp32 acc, mma.sync, R7-proven mainloop)
// with A fp32->fp16 conversion executed INSIDE the GEMM kernel as a
// claim-based cooperative pre-phase (idempotent, deadlock-free self-serve).
// B converted (transpose + gate-permute) by a small standalone kernel that
// also resets the claim flags each replay. out = [h | h | c].
// B columns permuted: col' = 4*u + gate.

#define MB   8192
#define KK   1024
#define NTOT 2048
#define UU   512
#define BM   128
#define BN   128
#define BK   32
#define KT   (KK / BK)              // 32 k-iterations
#define ROWB 80                     // smem row stride bytes
#define TILEB (128 * ROWB)          // 10240 per [128 x 32] fp16 tile
#define STAGEB (2 * TILEB)          // A, B
#define NSTG 4
#define SMEM_DYN (NSTG * STAGEB)    // 81920

#define NBAND 64                    // A bands (128 rows each)
#define NSUB  16                    // sub-items per band (8 rows each)

#define CONVB_BX (NTOT / 32)        // 64
#define CONVB_BLOCKS (CONVB_BX * (KK / 64))  // 1024

// -------- device scratch --------
__device__ __half g_A[(size_t)MB * KK];
__device__ __half g_B[(size_t)NTOT * KK];
__device__ unsigned g_subA[NBAND * NSUB];   // claim flags
__device__ unsigned g_doneA[NBAND];         // completed sub-items per band

// -------- helpers --------
__device__ __forceinline__ uint32_t s2u(const void* p) {
    uint32_t a;
    asm("{ .reg .u64 t; cvta.to.shared.u64 t, %1; cvt.u32.u64 %0, t; }"
        : "=r"(a) : "l"(p));
    return a;
}
__device__ __forceinline__ void cp16(uint32_t dst, const void* src) {
    asm volatile("cp.async.cg.shared.global [%0], [%1], 16;"
                 :: "r"(dst), "l"((unsigned long long)__cvta_generic_to_global(src))
                 : "memory");
}
#define CP_COMMIT() asm volatile("cp.async.commit_group;" ::: "memory")
#define CP_WAIT2()  asm volatile("cp.async.wait_group 2;" ::: "memory")

__device__ __forceinline__ void ldsm4(uint32_t* r, uint32_t addr) {
    asm volatile("ldmatrix.sync.aligned.m8n8.x4.shared.b16 {%0,%1,%2,%3}, [%4];"
                 : "=r"(r[0]), "=r"(r[1]), "=r"(r[2]), "=r"(r[3]) : "r"(addr));
}
__device__ __forceinline__ void mma16816(float* d, const uint32_t* a,
                                         const uint32_t* b) {
    asm volatile(
        "mma.sync.aligned.m16n8k16.row.col.f32.f16.f16.f32 "
        "{%0,%1,%2,%3}, {%4,%5,%6,%7}, {%8,%9}, {%0,%1,%2,%3};"
        : "+f"(d[0]), "+f"(d[1]), "+f"(d[2]), "+f"(d[3])
        : "r"(a[0]), "r"(a[1]), "r"(a[2]), "r"(a[3]), "r"(b[0]), "r"(b[1]));
}
__device__ __forceinline__ float ex2f(float x) {
    float y; asm("ex2.approx.f32 %0, %1;" : "=f"(y) : "f"(x)); return y;
}
__device__ __forceinline__ float rcpf(float x) {
    float y; asm("rcp.approx.f32 %0, %1;" : "=f"(y) : "f"(x)); return y;
}
__device__ __forceinline__ float sigf(float x) {
    return rcpf(1.0f + ex2f(-1.4426950408889634f * x));
}
__device__ __forceinline__ float tanhf_fast(float x) {
    return 1.0f - 2.0f * rcpf(1.0f + ex2f(2.8853900817779268f * x));
}

// -------- B conversion + flag reset --------
__global__ __launch_bounds__(256)
void conv_b(const float* __restrict__ W, const float* __restrict__ R)
{
    __shared__ __half s[64][34];
    if (blockIdx.x == CONVB_BLOCKS) {
        // reset claim flags for this replay (GEMM launches after us)
        for (int i = threadIdx.x; i < NBAND * NSUB; i += 256) g_subA[i] = 0u;
        if (threadIdx.x < NBAND) g_doneA[threadIdx.x] = 0u;
        return;
    }
    const int c0 = (blockIdx.x % CONVB_BX) * 32;
    const int k0 = (blockIdx.x / CONVB_BX) * 64;
    #pragma unroll
    for (int i = 0; i < 8; ++i) {
        int idx = threadIdx.x + i * 256;
        int kl = idx >> 5, cl = idx & 31;
        int colp = c0 + cl, u = colp >> 2, gate = colp & 3;
        int zcol = gate * 512 + u;
        int k = k0 + kl;
        float v = (k < 512) ? W[(size_t)k * NTOT + zcol]
                            : R[(size_t)(k - 512) * NTOT + zcol];
        s[kl][cl] = __float2half(v);
    }
    __syncthreads();
    const int cl = threadIdx.x >> 3;
    const int ks = (threadIdx.x & 7) * 8;
    __half tmp[8];
    #pragma unroll
    for (int j = 0; j < 8; ++j) tmp[j] = s[ks + j][cl];
    *(uint4*)&g_B[(size_t)(c0 + cl) * KK + k0 + ks] = *(uint4*)tmp;
}

// -------- fused GEMM + gates (R7 mainloop) with A-conversion pre-phase --------
__global__ __launch_bounds__(256, 2)
void lstm_mma(const float* __restrict__ X, const float* __restrict__ H,
              const float* __restrict__ Cprev,
              const float* __restrict__ bias,
              float* __restrict__ out)
{
    extern __shared__ __align__(128) char smem[];
    const uint32_t sm = s2u(smem);
    const int tid = threadIdx.x, wid = tid >> 5, lane = tid & 31;
    const int warp_m = wid >> 2;            // 0..1  (64 rows)
    const int warp_n = wid & 3;             // 0..3  (32 cols)
    const int m0 = blockIdx.y * BM;
    const int n0 = blockIdx.x * BN;
    const int band = blockIdx.y;

    // ---- pre-phase: ensure A band `band` is converted (self-serve claims) ----
    {
        __shared__ int sClaim;
        for (int s = 0; s < NSUB; ++s) {
            if (tid == 0)
                sClaim = (atomicExch(&g_subA[band * NSUB + s], 1u) == 0u);
            __syncthreads();
            if (sClaim) {
                const int r0 = band * 128 + s * 8;
                // 8 rows x 128 octs = 1024 octs; 4 per thread, coalesced, MLP=8
                float4 v[8];
                #pragma unroll
                for (int j = 0; j < 4; ++j) {
                    int o = tid + j * 256;
                    int r = r0 + (o >> 7);
                    int c8 = (o & 127) * 8;
                    const float4* src = (c8 < 512)
                        ? (const float4*)(X + (size_t)r * 512 + c8)
                        : (const float4*)(H + (size_t)r * 512 + (c8 - 512));
                    v[2 * j]     = src[0];
                    v[2 * j + 1] = src[1];
                }
                #pragma unroll
                for (int j = 0; j < 4; ++j) {
                    int o = tid + j * 256;
                    int r = r0 + (o >> 7);
                    __half h[8];
                    h[0] = __float2half(v[2*j].x);   h[1] = __float2half(v[2*j].y);
                    h[2] = __float2half(v[2*j].z);   h[3] = __float2half(v[2*j].w);
                    h[4] = __float2half(v[2*j+1].x); h[5] = __float2half(v[2*j+1].y);
                    h[6] = __float2half(v[2*j+1].z); h[7] = __float2half(v[2*j+1].w);
                    ((uint4*)g_A)[(size_t)r * 128 + (o & 127)] = *(uint4*)h;
                }
                __threadfence();
            }
            __syncthreads();
            if (sClaim && tid == 0) atomicAdd(&g_doneA[band], 1u);
            __syncthreads();
        }
        // wait for sub-items claimed by other (running) CTAs
        if (tid == 0) {
            unsigned v;
            do {
                asm volatile("ld.acquire.gpu.global.u32 %0, [%1];"
                             : "=r"(v) : "l"(&g_doneA[band]));
            } while (v < NSUB);
        }
        __syncthreads();
    }

    float acc[4][4][4];
    #pragma unroll
    for (int mi = 0; mi < 4; ++mi)
        #pragma unroll
        for (int ni = 0; ni < 4; ++ni)
            #pragma unroll
            for (int r = 0; r < 4; ++r) acc[mi][ni][r] = 0.0f;

    const int lr0 = tid >> 2, lseg = tid & 3;

    auto load_stage = [&](int t, int stg) {
        const uint32_t sb = sm + stg * STAGEB;
        const int kb = t * BK;
        #pragma unroll
        for (int j = 0; j < 2; ++j) {
            int r = lr0 + j * 64;
            uint32_t dst = sb + r * ROWB + lseg * 16;
            cp16(dst,         g_A + (size_t)(m0 + r) * KK + kb + lseg * 8);
            cp16(dst + TILEB, g_B + (size_t)(n0 + r) * KK + kb + lseg * 8);
        }
    };

    load_stage(0, 0); CP_COMMIT();
    load_stage(1, 1); CP_COMMIT();
    load_stage(2, 2); CP_COMMIT();

    const uint32_t aoff = (warp_m * 64 + (lane & 15)) * ROWB + ((lane >> 4) << 4);
    const uint32_t boff = TILEB
        + (warp_n * 32 + (lane & 7) + ((lane & 16) >> 1)) * ROWB + ((lane & 8) << 1);

    for (int t = 0; t < KT; ++t) {
        CP_WAIT2();
        __syncthreads();

        const uint32_t sb = sm + (t & 3) * STAGEB;
        #pragma unroll
        for (int ks = 0; ks < 2; ++ks) {
            const uint32_t kB = ks * 32;
            uint32_t ah[4][4], bh[2][4];
            #pragma unroll
            for (int mi = 0; mi < 4; ++mi)
                ldsm4(ah[mi], sb + aoff + mi * (16 * ROWB) + kB);
            #pragma unroll
            for (int nj = 0; nj < 2; ++nj)
                ldsm4(bh[nj], sb + boff + nj * (16 * ROWB) + kB);

            #pragma unroll
            for (int mi = 0; mi < 4; ++mi)
                #pragma unroll
                for (int ni = 0; ni < 4; ++ni)
                    mma16816(acc[mi][ni], ah[mi], &bh[ni >> 1][(ni & 1) * 2]);
        }

        if (t + 3 < KT) load_stage(t + 3, (t + 3) & 3);
        CP_COMMIT();
    }

    // ---- epilogue: stage z through smem (operand buffers dead) ----
    __syncthreads();
    float* zs = (float*)smem;               // [128][132]
    const int g = lane >> 2, c2 = (lane & 3) * 2;
    #pragma unroll
    for (int mi = 0; mi < 4; ++mi) {
        const int r0 = warp_m * 64 + mi * 16 + g;
        #pragma unroll
        for (int ni = 0; ni < 4; ++ni) {
            const int col = warp_n * 32 + ni * 8 + c2;
            zs[r0 * 132 + col]           = acc[mi][ni][0];
            zs[r0 * 132 + col + 1]       = acc[mi][ni][1];
            zs[(r0 + 8) * 132 + col]     = acc[mi][ni][2];
            zs[(r0 + 8) * 132 + col + 1] = acc[mi][ni][3];
        }
    }
    __syncthreads();

    const size_t BU = (size_t)MB * UU;
    #pragma unroll
    for (int i = 0; i < 16; ++i) {
        int q   = tid + i * 256;            // 0..4095
        int row = q >> 5;
        int ul  = q & 31;
        float4 zq = *(float4*)&zs[row * 132 + ul * 4];
        int u = blockIdx.x * 32 + ul;
        float zi = zq.x + __ldg(bias + u);
        float zf = zq.y + __ldg(bias + 512 + u);
        float zg = zq.z + __ldg(bias + 1024 + u);
        float zo = zq.w + __ldg(bias + 1536 + u);
        float cp = Cprev[(size_t)(m0 + row) * UU + u];
        float cn = sigf(zf) * cp + sigf(zi) * tanhf_fast(zg);
        float hv = sigf(zo) * tanhf_fast(cn);
        size_t o = (size_t)(m0 + row) * UU + u;
        out[o]          = hv;
        out[o + BU]     = hv;
        out[o + 2 * BU] = cn;
    }
}

// -------- launch --------
extern "C" void kernel_launch(void* const* d_in, const int* in_sizes, int n_in,
                              void* d_out, int out_size)
{
    const float* X    = (const float*)d_in[0];
    const float* H    = (const float*)d_in[1];
    const float* C    = (const float*)d_in[2];
    const float* W    = (const float*)d_in[3];
    const float* R    = (const float*)d_in[4];
    const float* bias = (const float*)d_in[5];
    float* out = (float*)d_out;

    static bool attr_done = false;
    if (!attr_done) {
        cudaFuncSetAttribute(lstm_mma,
                             cudaFuncAttributeMaxDynamicSharedMemorySize, SMEM_DYN);
        attr_done = true;
    }

    conv_b<<<CONVB_BLOCKS + 1, 256>>>(W, R);

    dim3 grid(NTOT / BN, MB / BM);          // (16, 64)
    lstm_mma<<<grid, 256, SMEM_DYN>>>(X, H, C, bias, out);
}

// round 16
// speedup vs baseline: 1.2321x; 1.2321x over previous
#include <cuda_runtime.h>
#include <cuda_fp16.h>
#include <cstdint>

// LSTM cell: single-pass fp16 GEMM (fp32 acc) via mma.sync + fused gate
// epilogue (R7/R13-proven config; GEMM measured at the m16n8k16 issue floor).
// z = [X|H] @ [W;R] (+bias); out = [h | h | c].
// B columns permuted: col' = 4*u + gate. Conversions merged in one launch;
// conv_a: MLP=8, coalesced, streaming (evict-first) source reads.

#define MB   8192
#define KK   1024
#define NTOT 2048
#define UU   512
#define BM   128
#define BN   128
#define BK   32
#define KT   (KK / BK)              // 32 k-iterations
#define ROWB 80                     // smem row stride bytes
#define TILEB (128 * ROWB)          // 10240 per [128 x 32] fp16 tile
#define STAGEB (2 * TILEB)          // A, B
#define NSTG 4
#define SMEM_DYN (NSTG * STAGEB)    // 81920; epilogue z-stage (67584) reuses it

#define CONVA_BLOCKS (MB * KK / 8 / 1024)  // 1024 blocks, 1024 octs each
#define CONVB_BX     (NTOT / 32)           // 64
#define CONVB_BLOCKS (CONVB_BX * (KK / 64))

// -------- device scratch --------
__device__ __half g_A[(size_t)MB * KK];
__device__ __half g_B[(size_t)NTOT * KK];

// -------- helpers --------
__device__ __forceinline__ uint32_t s2u(const void* p) {
    uint32_t a;
    asm("{ .reg .u64 t; cvta.to.shared.u64 t, %1; cvt.u32.u64 %0, t; }"
        : "=r"(a) : "l"(p));
    return a;
}
__device__ __forceinline__ void cp16(uint32_t dst, const void* src) {
    asm volatile("cp.async.cg.shared.global [%0], [%1], 16;"
                 :: "r"(dst), "l"((unsigned long long)__cvta_generic_to_global(src))
                 : "memory");
}
#define CP_COMMIT() asm volatile("cp.async.commit_group;" ::: "memory")
#define CP_WAIT2()  asm volatile("cp.async.wait_group 2;" ::: "memory")

__device__ __forceinline__ void ldsm4(uint32_t* r, uint32_t addr) {
    asm volatile("ldmatrix.sync.aligned.m8n8.x4.shared.b16 {%0,%1,%2,%3}, [%4];"
                 : "=r"(r[0]), "=r"(r[1]), "=r"(r[2]), "=r"(r[3]) : "r"(addr));
}
__device__ __forceinline__ void mma16816(float* d, const uint32_t* a,
                                         const uint32_t* b) {
    asm volatile(
        "mma.sync.aligned.m16n8k16.row.col.f32.f16.f16.f32 "
        "{%0,%1,%2,%3}, {%4,%5,%6,%7}, {%8,%9}, {%0,%1,%2,%3};"
        : "+f"(d[0]), "+f"(d[1]), "+f"(d[2]), "+f"(d[3])
        : "r"(a[0]), "r"(a[1]), "r"(a[2]), "r"(a[3]), "r"(b[0]), "r"(b[1]));
}
__device__ __forceinline__ float4 ldcs4(const float4* p) {
    float4 v;
    asm volatile("ld.global.cs.v4.f32 {%0,%1,%2,%3}, [%4];"
                 : "=f"(v.x), "=f"(v.y), "=f"(v.z), "=f"(v.w)
                 : "l"((unsigned long long)__cvta_generic_to_global(p)));
    return v;
}
__device__ __forceinline__ float ex2f(float x) {
    float y; asm("ex2.approx.f32 %0, %1;" : "=f"(y) : "f"(x)); return y;
}
__device__ __forceinline__ float rcpf(float x) {
    float y; asm("rcp.approx.f32 %0, %1;" : "=f"(y) : "f"(x)); return y;
}
__device__ __forceinline__ float sigf(float x) {
    return rcpf(1.0f + ex2f(-1.4426950408889634f * x));
}
__device__ __forceinline__ float tanhf_fast(float x) {
    return 1.0f - 2.0f * rcpf(1.0f + ex2f(2.8853900817779268f * x));
}

// -------- merged conversion kernel --------
// A-part: each block converts 1024 consecutive octs; thread handles octs
// {base + tid + j*256}: every LDG/STG fully coalesced, MLP=8, streaming reads.
__global__ __launch_bounds__(256)
void conv_all(const float* __restrict__ X, const float* __restrict__ H,
              const float* __restrict__ W, const float* __restrict__ R)
{
    __shared__ __half s[64][34];
    if (blockIdx.x < CONVA_BLOCKS) {
        const int base = blockIdx.x * 1024 + threadIdx.x;
        float4 v[8];
        #pragma unroll
        for (int j = 0; j < 4; ++j) {
            int o = base + j * 256;
            int row = o >> 7;
            int c8  = (o & 127) * 8;
            const float4* src = (c8 < 512)
                ? (const float4*)(X + (size_t)row * 512 + c8)
                : (const float4*)(H + (size_t)row * 512 + (c8 - 512));
            v[2 * j]     = ldcs4(src);
            v[2 * j + 1] = ldcs4(src + 1);
        }
        #pragma unroll
        for (int j = 0; j < 4; ++j) {
            __half h[8];
            h[0] = __float2half(v[2*j].x);   h[1] = __float2half(v[2*j].y);
            h[2] = __float2half(v[2*j].z);   h[3] = __float2half(v[2*j].w);
            h[4] = __float2half(v[2*j+1].x); h[5] = __float2half(v[2*j+1].y);
            h[6] = __float2half(v[2*j+1].z); h[7] = __float2half(v[2*j+1].w);
            ((uint4*)g_A)[base + j * 256] = *(uint4*)h;
        }
    } else {
        int bb = blockIdx.x - CONVA_BLOCKS;
        const int c0 = (bb % CONVB_BX) * 32;
        const int k0 = (bb / CONVB_BX) * 64;
        #pragma unroll
        for (int i = 0; i < 8; ++i) {
            int idx = threadIdx.x + i * 256;
            int kl = idx >> 5, cl = idx & 31;
            int colp = c0 + cl, u = colp >> 2, gate = colp & 3;
            int zcol = gate * 512 + u;
            int k = k0 + kl;
            float v = (k < 512) ? W[(size_t)k * NTOT + zcol]
                                : R[(size_t)(k - 512) * NTOT + zcol];
            s[kl][cl] = __float2half(v);
        }
        __syncthreads();
        const int cl = threadIdx.x >> 3;
        const int ks = (threadIdx.x & 7) * 8;
        __half tmp[8];
        #pragma unroll
        for (int j = 0; j < 8; ++j) tmp[j] = s[ks + j][cl];
        *(uint4*)&g_B[(size_t)(c0 + cl) * KK + k0 + ks] = *(uint4*)tmp;
    }
}

// -------- fused GEMM + gates (R7-proven, unchanged) --------
__global__ __launch_bounds__(256, 2)
void lstm_mma(const float* __restrict__ Cprev,
              const float* __restrict__ bias,
              float* __restrict__ out)
{
    extern __shared__ __align__(128) char smem[];
    const uint32_t sm = s2u(smem);
    const int tid = threadIdx.x, wid = tid >> 5, lane = tid & 31;
    const int warp_m = wid >> 2;            // 0..1  (64 rows)
    const int warp_n = wid & 3;             // 0..3  (32 cols)
    const int m0 = blockIdx.y * BM;
    const int n0 = blockIdx.x * BN;

    float acc[4][4][4];
    #pragma unroll
    for (int mi = 0; mi < 4; ++mi)
        #pragma unroll
        for (int ni = 0; ni < 4; ++ni)
            #pragma unroll
            for (int r = 0; r < 4; ++r) acc[mi][ni][r] = 0.0f;

    const int lr0 = tid >> 2, lseg = tid & 3;

    auto load_stage = [&](int t, int stg) {
        const uint32_t sb = sm + stg * STAGEB;
        const int kb = t * BK;
        #pragma unroll
        for (int j = 0; j < 2; ++j) {
            int r = lr0 + j * 64;
            uint32_t dst = sb + r * ROWB + lseg * 16;
            cp16(dst,         g_A + (size_t)(m0 + r) * KK + kb + lseg * 8);
            cp16(dst + TILEB, g_B + (size_t)(n0 + r) * KK + kb + lseg * 8);
        }
    };

    load_stage(0, 0); CP_COMMIT();
    load_stage(1, 1); CP_COMMIT();
    load_stage(2, 2); CP_COMMIT();

    const uint32_t aoff = (warp_m * 64 + (lane & 15)) * ROWB + ((lane >> 4) << 4);
    const uint32_t boff = TILEB
        + (warp_n * 32 + (lane & 7) + ((lane & 16) >> 1)) * ROWB + ((lane & 8) << 1);

    for (int t = 0; t < KT; ++t) {
        CP_WAIT2();
        __syncthreads();

        const uint32_t sb = sm + (t & 3) * STAGEB;
        #pragma unroll
        for (int ks = 0; ks < 2; ++ks) {
            const uint32_t kB = ks * 32;
            uint32_t ah[4][4], bh[2][4];
            #pragma unroll
            for (int mi = 0; mi < 4; ++mi)
                ldsm4(ah[mi], sb + aoff + mi * (16 * ROWB) + kB);
            #pragma unroll
            for (int nj = 0; nj < 2; ++nj)
                ldsm4(bh[nj], sb + boff + nj * (16 * ROWB) + kB);

            #pragma unroll
            for (int mi = 0; mi < 4; ++mi)
                #pragma unroll
                for (int ni = 0; ni < 4; ++ni)
                    mma16816(acc[mi][ni], ah[mi], &bh[ni >> 1][(ni & 1) * 2]);
        }

        if (t + 3 < KT) load_stage(t + 3, (t + 3) & 3);
        CP_COMMIT();
    }

    // ---- epilogue: stage z through smem (operand buffers dead) ----
    __syncthreads();
    float* zs = (float*)smem;               // [128][132]
    const int g = lane >> 2, c2 = (lane & 3) * 2;
    #pragma unroll
    for (int mi = 0; mi < 4; ++mi) {
        const int r0 = warp_m * 64 + mi * 16 + g;
        #pragma unroll
        for (int ni = 0; ni < 4; ++ni) {
            const int col = warp_n * 32 + ni * 8 + c2;
            zs[r0 * 132 + col]           = acc[mi][ni][0];
            zs[r0 * 132 + col + 1]       = acc[mi][ni][1];
            zs[(r0 + 8) * 132 + col]     = acc[mi][ni][2];
            zs[(r0 + 8) * 132 + col + 1] = acc[mi][ni][3];
        }
    }
    __syncthreads();

    const size_t BU = (size_t)MB * UU;
    #pragma unroll
    for (int i = 0; i < 16; ++i) {
        int q   = tid + i * 256;            // 0..4095
        int row = q >> 5;
        int ul  = q & 31;
        float4 zq = *(float4*)&zs[row * 132 + ul * 4];
        int u = blockIdx.x * 32 + ul;
        float zi = zq.x + __ldg(bias + u);
        float zf = zq.y + __ldg(bias + 512 + u);
        float zg = zq.z + __ldg(bias + 1024 + u);
        float zo = zq.w + __ldg(bias + 1536 + u);
        float cp = Cprev[(size_t)(m0 + row) * UU + u];
        float cn = sigf(zf) * cp + sigf(zi) * tanhf_fast(zg);
        float hv = sigf(zo) * tanhf_fast(cn);
        size_t o = (size_t)(m0 + row) * UU + u;
        out[o]          = hv;
        out[o + BU]     = hv;
        out[o + 2 * BU] = cn;
    }
}

// -------- launch --------
extern "C" void kernel_launch(void* const* d_in, const int* in_sizes, int n_in,
                              void* d_out, int out_size)
{
    const float* X    = (const float*)d_in[0];
    const float* H    = (const float*)d_in[1];
    const float* C    = (const float*)d_in[2];
    const float* W    = (const float*)d_in[3];
    const float* R    = (const float*)d_in[4];
    const float* bias = (const float*)d_in[5];
    float* out = (float*)d_out;

    static bool attr_done = false;
    if (!attr_done) {
        cudaFuncSetAttribute(lstm_mma,
                             cudaFuncAttributeMaxDynamicSharedMemorySize, SMEM_DYN);
        attr_done = true;
    }

    conv_all<<<CONVA_BLOCKS + CONVB_BLOCKS, 256>>>(X, H, W, R);

    dim3 grid(NTOT / BN, MB / BM);          // (16, 64)
    lstm_mma<<<grid, 256, SMEM_DYN>>>(C, bias, out);
}